// round 7
// baseline (speedup 1.0000x reference)
#include <cuda_runtime.h>
#include <math.h>

#define NBATCH 64
#define NSTEP  128
#define MEMD   128
#define NSLOT  20
#define HSLOT  10
#define OUTC   160
#define NGRP   7        // CTA groups per slot
#define BMAX   10       // max batches per CTA (group 0: 10, others: 9)
#define RSTR   12       // floats per mem_s row (48B)

__device__ float g_S [NBATCH * NSTEP * MEMD];
__device__ float g_O [NBATCH * NSTEP * OUTC];
__device__ float g_WK[OUTC * MEMD];
__device__ float g_BK[OUTC];
__device__ float g_VK[NSLOT * MEMD];
__device__ uint2 g_part[NSTEP][NSLOT][8];   // {value bits, tag=t+1}; 7 used, 64B/slot
__device__ float g_H [NBATCH * NSLOT * MEMD];

// ---------- helpers ----------
__device__ __forceinline__ void ffma2(unsigned long long &acc, unsigned long long a,
                                      unsigned long long b) {
    asm("fma.rn.f32x2 %0, %1, %2, %0;" : "+l"(acc) : "l"(a), "l"(b));
}
__device__ __forceinline__ unsigned long long add2(unsigned long long a,
                                                   unsigned long long b) {
    unsigned long long r;
    asm("add.rn.f32x2 %0, %1, %2;" : "=l"(r) : "l"(a), "l"(b));
    return r;
}
__device__ __forceinline__ unsigned long long pack2(float x) {
    unsigned long long r; asm("mov.b64 %0, {%1, %1};" : "=l"(r) : "f"(x)); return r;
}
__device__ __forceinline__ float2 up2(unsigned long long v) {
    float2 r; asm("mov.b64 {%0, %1}, %2;" : "=f"(r.x), "=f"(r.y) : "l"(v)); return r;
}
__device__ __forceinline__ unsigned smem_u32(const void* p) {
    return (unsigned)__cvta_generic_to_shared(p);
}
__device__ __forceinline__ void ldsA(unsigned addr, unsigned long long &m0,
                                     unsigned long long &m1) {
    asm("{\n\t"
        ".reg .b32 t0,t1,t2,t3;\n\t"
        "ld.shared.v4.b32 {t0,t1,t2,t3}, [%2];\n\t"
        "mov.b64 %0, {t0,t1};\n\t"
        "mov.b64 %1, {t2,t3};\n\t"
        "}" : "=l"(m0), "=l"(m1) : "r"(addr));
}
__device__ __forceinline__ unsigned long long ldsB(unsigned addr) {
    unsigned long long r;
    asm("{\n\t"
        ".reg .b32 t0,t1;\n\t"
        "ld.shared.v2.b32 {t0,t1}, [%1];\n\t"
        "mov.b64 %0, {t0,t1};\n\t"
        "}" : "=l"(r) : "r"(addr));
    return r;
}
__device__ __forceinline__ uint2 ldv2(const uint2* p) {
    uint2 v;
    asm volatile("ld.volatile.global.v2.u32 {%0,%1}, [%2];"
                 : "=r"(v.x), "=r"(v.y) : "l"(p) : "memory");
    return v;
}
__device__ __forceinline__ void stv2(uint2* p, uint2 v) {
    asm volatile("st.volatile.global.v2.u32 [%0], {%1,%2};"
                 :: "l"(p), "r"(v.x), "r"(v.y) : "memory");
}
__device__ __forceinline__ float sig(float x) { return 1.f / (1.f + __expf(-x)); }
__device__ __forceinline__ unsigned long long shflx64(unsigned long long v, int d) {
    return __shfl_xor_sync(~0u, v, d);
}

// ---------- prologue ----------
__global__ void k_setup(const float* __restrict__ Ww, const float* __restrict__ Wb,
                        const float* __restrict__ sk, const float* __restrict__ Vw,
                        const float* __restrict__ Vb) {
    int bid = blockIdx.x, tid = threadIdx.x;
    if (bid < NSLOT) {
        float acc = Vb[tid];
        const float* skr = sk + bid * MEMD;
        const float* vwr = Vw + tid * MEMD;
        #pragma unroll 8
        for (int m = 0; m < MEMD; m++) acc += skr[m] * vwr[m];
        g_VK[bid * MEMD + tid] = acc;
    } else if (bid == NSLOT) {
        for (int idx = tid; idx < OUTC * MEMD; idx += 128) {
            int c = idx >> 7, m = idx & 127;
            float v = 0.f;
            if (c < 128)      v = Ww[c * MEMD + m];
            else if (c < 148) v = sk[(c - 128) * MEMD + m];
            g_WK[idx] = v;
        }
        for (int idx = tid; idx < OUTC; idx += 128)
            g_BK[idx] = (idx < 128) ? Wb[idx] : 0.f;
    } else {
        // zero tag buffer: 10240 uint4 total, 40 blocks x 128 thr x 2
        int base = (bid - 21) * 128 + tid;
        ((uint4*)g_part)[base]        = make_uint4(0u, 0u, 0u, 0u);
        ((uint4*)g_part)[base + 5120] = make_uint4(0u, 0u, 0u, 0u);
    }
}

__global__ void k_gather(const int* __restrict__ ids, const float* __restrict__ E) {
    int idx = blockIdx.x * 256 + threadIdx.x;
    int row = idx >> 5, q = idx & 31;
    int b = row >> 7, t = row & 127;
    int tok = __ldg(&ids[b * 4096 + t]);
    ((float4*)g_S)[row * 32 + q] = ((const float4*)E)[tok * 32 + q];
}

__global__ void __launch_bounds__(256) k_gemm() {
    __shared__ float Ss[64][33];
    __shared__ float Ks[OUTC][33];
    int tid = threadIdx.x, row0 = blockIdx.x * 64;
    int tx = tid & 15, ty = tid >> 4;
    float acc[4][10];
    #pragma unroll
    for (int i = 0; i < 4; i++)
        #pragma unroll
        for (int j = 0; j < 10; j++) acc[i][j] = 0.f;
    for (int kk = 0; kk < 128; kk += 32) {
        #pragma unroll
        for (int i = 0; i < 8; i++) {
            int idx = tid + i * 256, r = idx >> 5, k = idx & 31;
            Ss[r][k] = g_S[(row0 + r) * 128 + kk + k];
        }
        #pragma unroll
        for (int i = 0; i < 20; i++) {
            int idx = tid + i * 256, c = idx >> 5, k = idx & 31;
            Ks[c][k] = g_WK[c * 128 + kk + k];
        }
        __syncthreads();
        #pragma unroll
        for (int k = 0; k < 32; k++) {
            float a[4], bv[10];
            #pragma unroll
            for (int i = 0; i < 4; i++)  a[i]  = Ss[ty * 4 + i][k];
            #pragma unroll
            for (int j = 0; j < 10; j++) bv[j] = Ks[tx * 10 + j][k];
            #pragma unroll
            for (int i = 0; i < 4; i++)
                #pragma unroll
                for (int j = 0; j < 10; j++) acc[i][j] = fmaf(a[i], bv[j], acc[i][j]);
        }
        __syncthreads();
    }
    #pragma unroll
    for (int i = 0; i < 4; i++)
        #pragma unroll
        for (int j = 0; j < 10; j++) {
            int r = row0 + ty * 4 + i, c = tx * 10 + j;
            g_O[r * OUTC + c] = acc[i][j] + g_BK[c];
        }
}

// ---------- persistent scan: slot-major, 7-CTA communicators ----------
__global__ void __launch_bounds__(512, 1) k_main(const float* __restrict__ Uw,
                                                 const float* __restrict__ Ub) {
    __shared__ __align__(16) float mem_s[128 * RSTR];          // raw mem[m][b]
    __shared__ __align__(16) unsigned long long hbuf[5 * 128]; // [bp][n]
    __shared__ float red2_s[16];
    __shared__ float inv_sm;

    const int tid = threadIdx.x;
    const int wid = tid >> 5, lane = tid & 31;
    const int cta = blockIdx.x;
    const int j   = cta / NGRP, g = cta % NGRP;
    const int b0  = 9 * g + (g ? 1 : 0);
    const int nb  = g ? 9 : 10;

    // ---- matmul mapping: ntile 0..63 (NT=2 cols), msplit 0..7 ----
    const int ntile = (wid << 2) | (lane >> 3);
    const int n0 = ntile << 1;
    const int msplit = lane & 7;
    float uw[2][16];
    #pragma unroll
    for (int nt = 0; nt < 2; nt++)
        #pragma unroll
        for (int k = 0; k < 16; k++)
            uw[nt][k] = Uw[(n0 + nt) * 128 + k * 8 + msplit];

    // ---- epilogue mapping: batch = warp, 4 n per lane ----
    const int eb = wid;                 // 0..15; valid epilogue warps: eb < 10
    const int en4 = lane << 2;
    const bool ewarp = (eb < BMAX);
    const bool valid = (eb < nb);
    const int batch = b0 + (valid ? eb : 0);

    float4 uvk4;
    if (ewarp) {
        float4 u = *(const float4*)(Ub + en4);
        float4 v = *(const float4*)(g_VK + j * MEMD + en4);
        uvk4 = make_float4(u.x + v.x, u.y + v.y, u.z + v.z, u.w + v.w);
    }

    for (int idx = tid; idx < 128 * RSTR; idx += 512) mem_s[idx] = 0.f;

    float memv[4] = {0.f, 0.f, 0.f, 0.f};

    // staging (registers, double-buffered)
    const float* Sb = g_S + batch * 128 * 128;
    const float* Ob = g_O + batch * 128 * OUTC;
    float4 s4c = make_float4(0,0,0,0), w4c = s4c, s4n, w4n;
    float skc = 0.f, skn;
    if (ewarp) {
        s4c = *(const float4*)(Sb + en4);
        w4c = *(const float4*)(Ob + en4);
        float t0 = (lane == 0) ? Ob[128 + j] : 0.f;
        skc = __shfl_sync(~0u, t0, 0);
    }
    if (tid == 0) inv_sm = 1.f;         // t=0: mem is exactly zero
    __syncthreads();

    const unsigned mbase = smem_u32(mem_s) + msplit * (RSTR * 4);
    const unsigned hbase = smem_u32(hbuf);

    for (int t = 0; t < NSTEP; t++) {
        // ---- A. prefetch next-step staging ----
        {
            int tn = (t + 1) & 127;
            if (ewarp) {
                s4n = *(const float4*)(Sb + tn * 128 + en4);
                w4n = *(const float4*)(Ob + tn * OUTC + en4);
                float t0 = (lane == 0) ? Ob[tn * OUTC + 128 + j] : 0.f;
                skn = __shfl_sync(~0u, t0, 0);
            }
        }

        // ---- B. gate dot from registers (per-warp, batch eb) ----
        float rawdot = 0.f;
        if (ewarp) {
            rawdot = s4c.x * memv[0] + s4c.y * memv[1]
                   + s4c.z * memv[2] + s4c.w * memv[3];
            #pragma unroll
            for (int s = 16; s; s >>= 1)
                rawdot += __shfl_xor_sync(~0u, rawdot, s);
        }

        // ---- C. matmul: 16 m-rows x (3 LDS + 10 FFMA2), NT=2 ----
        unsigned long long acc[2][5];
        #pragma unroll
        for (int nt = 0; nt < 2; nt++)
            #pragma unroll
            for (int p = 0; p < 5; p++) acc[nt][p] = 0ull;
        #pragma unroll
        for (int k = 0; k < 16; k++) {
            unsigned long long m0, m1, m2, m3, m4;
            unsigned a = mbase + k * (8 * RSTR * 4);
            ldsA(a, m0, m1);
            ldsA(a + 16, m2, m3);
            m4 = ldsB(a + 32);
            #pragma unroll
            for (int nt = 0; nt < 2; nt++) {
                unsigned long long u2 = pack2(uw[nt][k]);
                ffma2(acc[nt][0], u2, m0);
                ffma2(acc[nt][1], u2, m1);
                ffma2(acc[nt][2], u2, m2);
                ffma2(acc[nt][3], u2, m3);
                ffma2(acc[nt][4], u2, m4);
            }
        }
        #pragma unroll
        for (int d = 1; d < 8; d <<= 1)
            #pragma unroll
            for (int nt = 0; nt < 2; nt++)
                #pragma unroll
                for (int p = 0; p < 5; p++)
                    acc[nt][p] = add2(acc[nt][p], shflx64(acc[nt][p], d));
        if (msplit == 0) {
            #pragma unroll
            for (int p = 0; p < 5; p++) {
                ulonglong2 v; v.x = acc[0][p]; v.y = acc[1][p];
                *(ulonglong2*)&hbuf[p * 128 + n0] = v;
            }
        }

        // ---- D. poll norms (single lane; one 64B sector) ----
        if (t && tid == 0) {
            const uint2* pp = &g_part[t - 1][j][0];
            const unsigned want = (unsigned)t;
            uint2 v0, v1, v2, v3, v4, v5, v6;
            do {
                v0 = ldv2(pp);     v1 = ldv2(pp + 1); v2 = ldv2(pp + 2);
                v3 = ldv2(pp + 3); v4 = ldv2(pp + 4); v5 = ldv2(pp + 5);
                v6 = ldv2(pp + 6);
            } while ((v0.y ^ want) | (v1.y ^ want) | (v2.y ^ want) |
                     (v3.y ^ want) | (v4.y ^ want) | (v5.y ^ want) | (v6.y ^ want));
            float a = __uint_as_float(v0.x) + __uint_as_float(v1.x)
                    + __uint_as_float(v2.x) + __uint_as_float(v3.x)
                    + __uint_as_float(v4.x) + __uint_as_float(v5.x)
                    + __uint_as_float(v6.x);
            inv_sm = rsqrtf(a);
        }
        __syncthreads();   // hbuf + inv_sm visible

        // ---- F. epilogue (warps 0..9, batch eb) ----
        if (ewarp) {
            const float inv = inv_sm;
            const int bp = eb >> 1;
            ulonglong2 p0 = *(const ulonglong2*)&hbuf[bp * 128 + en4];
            ulonglong2 p1 = *(const ulonglong2*)&hbuf[bp * 128 + en4 + 2];
            float2 f0 = up2(p0.x), f1 = up2(p0.y), f2 = up2(p1.x), f3 = up2(p1.y);
            float hr0 = (eb & 1) ? f0.y : f0.x;
            float hr1 = (eb & 1) ? f1.y : f1.x;
            float hr2 = (eb & 1) ? f2.y : f2.x;
            float hr3 = (eb & 1) ? f3.y : f3.x;

            float gg = sig(fmaf(inv, rawdot, skc));
            float h0 = fmaxf(fmaf(inv, hr0, uvk4.x + w4c.x), 0.f);
            float h1 = fmaxf(fmaf(inv, hr1, uvk4.y + w4c.y), 0.f);
            float h2 = fmaxf(fmaf(inv, hr2, uvk4.z + w4c.z), 0.f);
            float h3 = fmaxf(fmaf(inv, hr3, uvk4.w + w4c.w), 0.f);
            if (valid) {
                memv[0] = fmaf(memv[0], inv, gg * h0);
                memv[1] = fmaf(memv[1], inv, gg * h1);
                memv[2] = fmaf(memv[2], inv, gg * h2);
                memv[3] = fmaf(memv[3], inv, gg * h3);
            }
            float sq = memv[0]*memv[0] + memv[1]*memv[1]
                     + memv[2]*memv[2] + memv[3]*memv[3];
            #pragma unroll
            for (int s = 16; s; s >>= 1) sq += __shfl_xor_sync(~0u, sq, s);
            if (lane == 0) red2_s[eb] = sq;

            // write raw mem(t+1) column
            mem_s[(en4 + 0) * RSTR + eb] = memv[0];
            mem_s[(en4 + 1) * RSTR + eb] = memv[1];
            mem_s[(en4 + 2) * RSTR + eb] = memv[2];
            mem_s[(en4 + 3) * RSTR + eb] = memv[3];
            s4c = s4n; w4c = w4n; skc = skn;
        }
        __syncthreads();   // mem(t+1) + red2_s visible

        // ---- H. publish tagged sumsq partial (1 per CTA) ----
        if (wid == 0) {
            float v = (lane < BMAX) ? red2_s[lane] : 0.f;
            #pragma unroll
            for (int s = 16; s; s >>= 1) v += __shfl_xor_sync(~0u, v, s);
            if (lane == 0) {
                uint2 pkt; pkt.x = __float_as_uint(v); pkt.y = (unsigned)(t + 1);
                stv2(&g_part[t][j][g], pkt);
            }
        }
    }

    // ---- final normalization + writeback ----
    if (tid == 0) {
        const uint2* pp = &g_part[NSTEP - 1][j][0];
        const unsigned want = (unsigned)NSTEP;
        uint2 v0, v1, v2, v3, v4, v5, v6;
        do {
            v0 = ldv2(pp);     v1 = ldv2(pp + 1); v2 = ldv2(pp + 2);
            v3 = ldv2(pp + 3); v4 = ldv2(pp + 4); v5 = ldv2(pp + 5);
            v6 = ldv2(pp + 6);
        } while ((v0.y ^ want) | (v1.y ^ want) | (v2.y ^ want) |
                 (v3.y ^ want) | (v4.y ^ want) | (v5.y ^ want) | (v6.y ^ want));
        float a = __uint_as_float(v0.x) + __uint_as_float(v1.x)
                + __uint_as_float(v2.x) + __uint_as_float(v3.x)
                + __uint_as_float(v4.x) + __uint_as_float(v5.x)
                + __uint_as_float(v6.x);
        inv_sm = rsqrtf(a);
    }
    __syncthreads();
    if (ewarp && valid) {
        const float inv = inv_sm;
        float* gh = g_H + batch * (NSLOT * MEMD) + j * MEMD;
        gh[en4 + 0] = memv[0] * inv;
        gh[en4 + 1] = memv[1] * inv;
        gh[en4 + 2] = memv[2] * inv;
        gh[en4 + 3] = memv[3] * inv;
    }
}

// ---------- epilogue ----------
__global__ void k_epi(const int* __restrict__ q, const int* __restrict__ ans,
                      const float* __restrict__ E, const float* __restrict__ Hw,
                      const float* __restrict__ Hb, float* __restrict__ out) {
    __shared__ float red[4][NSLOT];
    __shared__ float p_s[NSLOT];
    __shared__ float u_s[MEMD];
    __shared__ float yr[4][2];
    int b = blockIdx.x, n = threadIdx.x, w = n >> 5, l = n & 31;

    float qv = 0.f;
    #pragma unroll
    for (int i = 0; i < 16; i++) qv += E[q[b * 16 + i] * MEMD + n];
    qv *= (1.f / 16.f);
    float a1 = 0.f, a2 = 0.f;
    #pragma unroll
    for (int i = 0; i < 8; i++) {
        a1 += E[ans[(b * 8 + i) * 2 + 0] * MEMD + n];
        a2 += E[ans[(b * 8 + i) * 2 + 1] * MEMD + n];
    }
    a1 *= 0.125f; a2 *= 0.125f;

    float hv[NSLOT], p[NSLOT];
    #pragma unroll
    for (int jj = 0; jj < NSLOT; jj++) {
        hv[jj] = g_H[b * (NSLOT * MEMD) + jj * MEMD + n];
        p[jj] = hv[jj] * qv;
    }
    #pragma unroll
    for (int s = 16; s; s >>= 1)
        #pragma unroll
        for (int jj = 0; jj < NSLOT; jj++) p[jj] += __shfl_xor_sync(~0u, p[jj], s);
    if (l == 0) {
        #pragma unroll
        for (int jj = 0; jj < NSLOT; jj++) red[w][jj] = p[jj];
    }
    __syncthreads();
    if (n == 0) {
        float d[NSLOT], mx = -1e30f;
        #pragma unroll
        for (int jj = 0; jj < NSLOT; jj++) {
            d[jj] = red[0][jj] + red[1][jj] + red[2][jj] + red[3][jj];
            mx = fmaxf(mx, d[jj]);
        }
        float sm = 0.f;
        #pragma unroll
        for (int jj = 0; jj < NSLOT; jj++) { d[jj] = expf(d[jj] - mx); sm += d[jj]; }
        float inv = 1.f / sm;
        #pragma unroll
        for (int jj = 0; jj < NSLOT; jj++) p_s[jj] = d[jj] * inv;
    }
    __syncthreads();

    float u = 0.f;
    #pragma unroll
    for (int jj = 0; jj < NSLOT; jj++) u = fmaf(p_s[jj], hv[jj], u);
    u_s[n] = u;
    __syncthreads();

    float r = qv + Hb[n];
    const float* hwr = Hw + n * MEMD;
    #pragma unroll 8
    for (int m = 0; m < MEMD; m++) r = fmaf(u_s[m], hwr[m], r);
    r = fmaxf(r, 0.f);

    float y1 = r * a1, y2 = r * a2;
    #pragma unroll
    for (int s = 16; s; s >>= 1) {
        y1 += __shfl_xor_sync(~0u, y1, s);
        y2 += __shfl_xor_sync(~0u, y2, s);
    }
    if (l == 0) { yr[w][0] = y1; yr[w][1] = y2; }
    __syncthreads();
    if (n == 0) {
        float s1 = yr[0][0] + yr[1][0] + yr[2][0] + yr[3][0];
        float s2 = yr[0][1] + yr[1][1] + yr[2][1] + yr[3][1];
        float mx = fmaxf(s1, s2);
        float e1 = expf(s1 - mx), e2 = expf(s2 - mx);
        float inv = 1.f / (e1 + e2);
        out[b * 2 + 0] = e1 * inv;
        out[b * 2 + 1] = e2 * inv;
    }
}

extern "C" void kernel_launch(void* const* d_in, const int* in_sizes, int n_in,
                              void* d_out, int out_size) {
    const int*   input_ids = (const int*)  d_in[0];
    const int*   question  = (const int*)  d_in[1];
    const int*   ans       = (const int*)  d_in[2];
    const float* E         = (const float*)d_in[3];
    const float* Uw        = (const float*)d_in[4];
    const float* Ub        = (const float*)d_in[5];
    const float* Vw        = (const float*)d_in[6];
    const float* Vb        = (const float*)d_in[7];
    const float* Ww        = (const float*)d_in[8];
    const float* Wb        = (const float*)d_in[9];
    const float* sk        = (const float*)d_in[10];
    const float* Hw        = (const float*)d_in[11];
    const float* Hb        = (const float*)d_in[12];
    float* out = (float*)d_out;

    k_setup <<<61, 128>>>(Ww, Wb, sk, Vw, Vb);
    k_gather<<<1024, 256>>>(input_ids, E);
    k_gemm  <<<128, 256>>>();
    k_main  <<<140, 512>>>(Uw, Ub);
    k_epi   <<<64, 128>>>(question, ans, E, Hw, Hb, out);
}